// round 8
// baseline (speedup 1.0000x reference)
#include <cuda_runtime.h>

#define NCLS 19
#define HW_   (512*1024)        // 2^19
#define NPIX  (4*HW_)           // 2,097,152
#define GRIDP 592               // 4 CTAs/SM * 148 SMs -> co-resident at <=64 regs
#define TB    256
#define PPT   14                // pixels/thread: 592*256*14 = 2,121,728 >= NPIX
#define INV   0xFFFFFFFFu

// ---- static scratch (zero-initialized at load; self-cleaned each call) ----
__device__ unsigned g_hist0[4096];
__device__ unsigned g_hist1[4096];
__device__ unsigned g_cnt2[256];
__device__ float    g_sum2[256];
__device__ double   g_sumHi;
__device__ unsigned g_cntHi;
__device__ unsigned g_pref0p1, g_pref01p1, g_k1, g_k2;   // prefix+1; 0 = invalid
__device__ unsigned g_done0, g_done1, g_done2, g_flag0, g_flag1;

// ------------------------------------------------------------------
// Descending scan over a 4096-bin histogram; winning thread writes the
// (bin, rank) into shared outputs. 256 threads, 16 bins each.
__device__ void scan4096(const unsigned* __restrict__ hist, unsigned k,
                         unsigned* ss, unsigned* out_bin, unsigned* out_r,
                         bool derive_k) {
    int t = threadIdx.x;
    unsigned cnt[16]; unsigned myv = 0;
    #pragma unroll
    for (int i = 0; i < 16; i++) { cnt[i] = __ldcg(&hist[4095 - (t * 16 + i)]); myv += cnt[i]; }
    ss[t] = myv; __syncthreads();
    for (int off = 1; off < 256; off <<= 1) {
        unsigned x = (t >= off) ? ss[t - off] : 0u;
        __syncthreads(); ss[t] += x; __syncthreads();
    }
    if (derive_k) {
        unsigned total = ss[255];          // uniform
        if (total == 0) return;            // *out_bin stays INV
        unsigned nk = (unsigned)(0.7f * (float)total);
        if (nk < 100000u) nk = 100000u;
        if (nk > total)   nk = total;
        k = nk;
    }
    unsigned hi = ss[t], lo = hi - myv;
    if (k > lo && k <= hi) {               // exactly one thread wins
        unsigned cum = lo;
        #pragma unroll
        for (int i = 0; i < 16; i++) {
            cum += cnt[i];
            if (k <= cum) {
                *out_bin = 4095u - (t * 16 + i);
                *out_r   = k - (cum - cnt[i]);
                break;
            }
        }
    }
}

// ------------------------------------------------------------------
// Single persistent kernel. Phase A: one pixel/thread/iter, 19 scalar
// loads batched into regs (high MLP), losses kept in registers.
__global__ void __launch_bounds__(TB, 4) k_ohem(const float* __restrict__ logits,
                                                const void* __restrict__ tgt_raw,
                                                float* __restrict__ out) {
    __shared__ unsigned sh[4096];       // hist staging / byte-phase cnt+sum
    __shared__ unsigned s_ss[256];
    __shared__ double   s_rd[256];
    __shared__ unsigned s_rc[256];
    __shared__ unsigned s_bin, s_r;
    __shared__ bool     s_last;

    int t = threadIdx.x;
    for (int i = t; i < 4096; i += TB) sh[i] = 0;
    __syncthreads();

    // ---- dtype detection (uniform; 8 cached loads) ----
    const long long* tdet = (const long long*)tgt_raw;
    int tmode = 1;
    #pragma unroll
    for (int i = 0; i < 8; i++) {
        long long x = tdet[i];
        if (x < 0 || x >= (long long)NCLS) tmode = 0;
    }
    const long long* t64 = (const long long*)tgt_raw;
    const int*       t32 = (const int*)tgt_raw;

    // ---- Phase A: per-pixel NLL, losses -> registers, hist0 -> shared ----
    unsigned loss[PPT];
    const int stride = GRIDP * TB;
    const int p0 = blockIdx.x * TB + t;

    #pragma unroll
    for (int i = 0; i < PPT; i++) {
        int p = p0 + i * stride;
        unsigned lb = 0;
        if (i < PPT - 1 || p < NPIX) {            // only last iter needs check
            int n  = p >> 19;
            int hw = p & (HW_ - 1);
            const float* base = logits + (size_t)n * (NCLS * (size_t)HW_) + hw;
            int tt = tmode ? (int)__ldg(t64 + p) : __ldg(t32 + p);

            float v[NCLS];                         // 19 independent loads, batched
            #pragma unroll
            for (int c = 0; c < NCLS; c++) v[c] = __ldg(base + (size_t)c * HW_);

            float s = 0.f, xt = 0.f;
            #pragma unroll
            for (int c = 0; c < NCLS; c++) {
                s += __expf(v[c]);
                if (c == tt) xt = v[c];
            }
            float l = __logf(s) - xt;
            lb = __float_as_uint(l);
            if (l > 0.f) atomicAdd(&sh[lb >> 20], 1u);
        }
        loss[i] = lb;
    }
    __syncthreads();
    for (int i = t; i < 4096; i += TB) {
        unsigned c = sh[i];
        if (c) atomicAdd(&g_hist0[i], c);
    }
    __threadfence();
    __syncthreads();                       // all hist0 atomics issued
    if (t == 0) s_last = (atomicAdd(&g_done0, 1u) == GRIDP - 1);
    __syncthreads();

    // re-zero sh for hist1 while waiting
    for (int i = t; i < 4096; i += TB) sh[i] = 0;

    // ---- scan0 by last-arriving block ----
    if (s_last) {
        if (t == 0) { s_bin = INV; s_r = 0; }
        __syncthreads();
        scan4096(g_hist0, 0, s_ss, &s_bin, &s_r, true);
        __syncthreads();
        if (t == 0) {
            if (s_bin != INV) { g_pref0p1 = s_bin + 1u; g_k1 = s_r; }
            __threadfence();
            atomicExch(&g_flag0, 1u);
        }
    }
    if (t == 0) { while (*(volatile unsigned*)&g_flag0 == 0u) __nanosleep(64); }
    __syncthreads();
    __threadfence();
    unsigned p0p1 = *(volatile unsigned*)&g_pref0p1;

    // ---- hist1 from registers ----
    if (p0p1 != 0u) {
        unsigned pref0 = p0p1 - 1u;
        #pragma unroll
        for (int i = 0; i < PPT; i++) {
            unsigned b = loss[i];
            if ((int)b > 0 && (b >> 20) == pref0) atomicAdd(&sh[(b >> 8) & 0xFFFu], 1u);
        }
        __syncthreads();
        for (int i = t; i < 4096; i += TB) {
            unsigned c = sh[i];
            if (c) atomicAdd(&g_hist1[i], c);
        }
    }
    __threadfence();
    __syncthreads();                       // all hist1 atomics issued
    if (t == 0) s_last = (atomicAdd(&g_done1, 1u) == GRIDP - 1);
    __syncthreads();

    // ---- scan1 by last-arriving block ----
    if (s_last) {
        if (t == 0) { s_bin = INV; s_r = 0; }
        __syncthreads();
        if (p0p1 != 0u) {
            scan4096(g_hist1, __ldcg(&g_k1), s_ss, &s_bin, &s_r, false);
            __syncthreads();
        }
        if (t == 0) {
            if (p0p1 != 0u && s_bin != INV) {
                g_pref01p1 = ((((p0p1 - 1u) << 12) | s_bin)) + 1u;
                g_k2 = s_r;
            }
            __threadfence();
            atomicExch(&g_flag1, 1u);
        }
    }
    if (t == 0) { while (*(volatile unsigned*)&g_flag1 == 0u) __nanosleep(64); }
    __syncthreads();
    __threadfence();
    unsigned p01p1 = *(volatile unsigned*)&g_pref01p1;

    // ---- byte-level phase from registers ----
    unsigned* s_cnt2 = sh;                    // [0..255]
    float*    s_fs2  = (float*)(sh + 256);    // [256..511]
    for (int i = t; i < 256; i += TB) { s_cnt2[i] = 0; s_fs2[i] = 0.f; }
    __syncthreads();

    float    fHi = 0.f;                       // <=14 exact float adds
    unsigned cHi = 0;
    if (p01p1 != 0u) {
        unsigned pref01 = p01p1 - 1u;
        #pragma unroll
        for (int i = 0; i < PPT; i++) {
            unsigned bb = loss[i];
            if ((int)bb > 0) {
                unsigned p24 = bb >> 8;
                if (p24 > pref01) { fHi += __uint_as_float(bb); cHi++; }
                else if (p24 == pref01) {
                    atomicAdd(&s_cnt2[bb & 0xFFu], 1u);
                    atomicAdd(&s_fs2[bb & 0xFFu], __uint_as_float(bb));
                }
            }
        }
    } else {
        // no valid pixels: plain mean over everything (inactive slots add 0)
        #pragma unroll
        for (int i = 0; i < PPT; i++) fHi += __uint_as_float(loss[i]);
    }

    s_rd[t] = (double)fHi; s_rc[t] = cHi;
    __syncthreads();
    for (int off = 128; off > 0; off >>= 1) {
        if (t < off) { s_rd[t] += s_rd[t + off]; s_rc[t] += s_rc[t + off]; }
        __syncthreads();
    }
    if (t == 0) {
        atomicAdd(&g_sumHi, s_rd[0]);
        if (s_rc[0]) atomicAdd(&g_cntHi, s_rc[0]);
    }
    for (int i = t; i < 256; i += TB) {
        if (s_cnt2[i]) { atomicAdd(&g_cnt2[i], s_cnt2[i]); atomicAdd(&g_sum2[i], s_fs2[i]); }
    }
    __threadfence();
    __syncthreads();                       // all byte-phase atomics issued
    if (t == 0) s_last = (atomicAdd(&g_done2, 1u) == GRIDP - 1);
    __syncthreads();
    if (!s_last) return;

    // ---- final mean (last block only) ----
    if (t == 0) {
        double outv;
        if (p01p1 == 0u) {
            outv = __ldcg(&g_sumHi) / (double)NPIX;
        } else {
            unsigned k2 = __ldcg(&g_k2);
            unsigned cum = 0;
            double ssum = 0.0;
            for (int b = 255; b >= 0; b--) {
                unsigned c = __ldcg(&g_cnt2[b]);
                ssum += (double)__ldcg(&g_sum2[b]);
                cum  += c;
                if (cum >= k2) break;            // threshold byte reached (ties kept)
            }
            double   ktot = __ldcg(&g_sumHi) + ssum;
            unsigned kcnt = __ldcg(&g_cntHi) + cum;
            if (kcnt == 0) kcnt = 1;
            outv = ktot / (double)kcnt;
        }
        out[0] = (float)outv;
    }
    __syncthreads();

    // ---- self-clean for next graph replay ----
    for (int i = t; i < 4096; i += TB) { g_hist0[i] = 0; g_hist1[i] = 0; }
    for (int i = t; i < 256;  i += TB) { g_cnt2[i] = 0; g_sum2[i] = 0.f; }
    if (t == 0) {
        g_sumHi = 0.0; g_cntHi = 0;
        g_pref0p1 = 0; g_pref01p1 = 0; g_k1 = 0; g_k2 = 0;
        g_done0 = 0; g_done1 = 0; g_done2 = 0;
        g_flag0 = 0; g_flag1 = 0;
        __threadfence();
    }
}

// ------------------------------------------------------------------
extern "C" void kernel_launch(void* const* d_in, const int* in_sizes, int n_in,
                              void* d_out, int out_size) {
    const float* logits = (const float*)d_in[0];
    const void*  tgt    = d_in[1];
    float* out = (float*)d_out;

    k_ohem<<<GRIDP, TB>>>(logits, tgt, out);
}